// round 13
// baseline (speedup 1.0000x reference)
#include <cuda_runtime.h>
#include <math.h>

#define BB 32
#define HH 256
#define LL 2048
#define VV 50257
#define K2H 512
#define NBLK 393          // ceil(VV/128)
#define NKS 8             // k-splits for gates
#define NCH 64            // attention l-chunks (32 rows each)
#define GT 32
#define KT 96
#define WSD 34

// d_out layout: log_probs[B*V], h_new[B*H], c_new[B*H], attn_weights[B*L]
#define OUT_H  (BB * VV)
#define OUT_C  (OUT_H + BB * HH)
#define OUT_AW (OUT_C + BB * HH)

// ---------------- scratch ----------------
__device__ __align__(16) float g_wpart[4 * 256];        // partial We^T v
__device__ __align__(16) float g_scores[BB * LL];
__device__ __align__(16) float g_ms[BB * NCH];          // per-chunk max
__device__ __align__(16) float g_Ss[BB * NCH];          // per-chunk expsum
__device__ __align__(16) float g_part[BB * NCH * HH];   // per-chunk weighted partials
__device__ __align__(16) float g_xT[768 * 32];          // [k][b] LSTM input transposed
__device__ __align__(16) float g_gpart[NKS * 1024 * 32];// gate partials [ks][g][b]
__device__ __align__(16) float g_x2[BB * K2H];          // concat(h_new, attnap) per b
__device__ __align__(16) float g_lsem[NBLK * 32];       // per-vblock max per b
__device__ __align__(16) float g_lses[NBLK * 32];       // per-vblock expsum per b

// phase flags (zero-initialized; reset each launch by k_sub)
__device__ int g_fW, g_f1, g_f2, g_f3;

static __device__ __forceinline__ unsigned long long ffma2(
    unsigned long long a, unsigned long long b, unsigned long long c) {
    unsigned long long d;
    asm("fma.rn.f32x2 %0, %1, %2, %3;" : "=l"(d) : "l"(a), "l"(b), "l"(c));
    return d;
}

static __device__ __forceinline__ float sigf(float x) { return 1.0f / (1.0f + expf(-x)); }

static __device__ __forceinline__ void spin_ge(int* flag, int target, int tid) {
    if (tid == 0) { while (*((volatile int*)flag) < target) { } }
    __syncthreads();
    __threadfence();
}

static __device__ __forceinline__ void arrive(int* flag) {
    __threadfence();
    atomicAdd(flag, 1);
}

// ================= K1: attention pass 1 (+ fused w-partials) =================
__global__ void kA(const float* __restrict__ enc,
                   const float* __restrict__ W_attn,
                   const float* __restrict__ vvec) {
    __shared__ float es[32 * 256];      // 32 KB
    __shared__ float w_s[256];
    __shared__ float score_s[32];
    __shared__ float esc_s[32];
    __shared__ float mred_s[1];
    int c = blockIdx.x, b = blockIdx.y;
    int flat = c + 64 * b;
    int t = threadIdx.x;
    int lane = t & 31, wid = t >> 5;

    // blocks 0-3: compute w-partials first (wave-1 resident by placement)
    if (flat < 4) {
        int kb = flat * 64;
        float a0 = 0, a1 = 0, a2 = 0, a3 = 0;
        #pragma unroll 4
        for (int i = 0; i < 64; i += 4) {
            a0 = fmaf(vvec[kb + i + 0], W_attn[(kb + i + 0) * 512 + 256 + t], a0);
            a1 = fmaf(vvec[kb + i + 1], W_attn[(kb + i + 1) * 512 + 256 + t], a1);
            a2 = fmaf(vvec[kb + i + 2], W_attn[(kb + i + 2) * 512 + 256 + t], a2);
            a3 = fmaf(vvec[kb + i + 3], W_attn[(kb + i + 3) * 512 + 256 + t], a3);
        }
        g_wpart[flat * 256 + t] = (a0 + a1) + (a2 + a3);
        __syncthreads();
        if (t == 0) arrive(&g_fW);
    }

    // stage enc chunk (w-independent)
    const float4* e4 = (const float4*)(enc + ((size_t)b * LL + c * 32) * HH);
    float4* s4 = (float4*)es;
    #pragma unroll
    for (int i = 0; i < 8; i++) s4[t + 256 * i] = e4[t + 256 * i];

    spin_ge(&g_fW, 4, t);
    w_s[t] = g_wpart[t] + g_wpart[256 + t] + g_wpart[512 + t] + g_wpart[768 + t];
    __syncthreads();

    const float4* w4 = (const float4*)w_s;
    float4 wa = w4[lane], wb = w4[32 + lane];
    #pragma unroll
    for (int r = wid; r < 32; r += 8) {
        const float4* row = (const float4*)(es + r * 256);
        float4 a = row[lane], cc = row[32 + lane];
        float s = a.x * wa.x + a.y * wa.y + a.z * wa.z + a.w * wa.w
                + cc.x * wb.x + cc.y * wb.y + cc.z * wb.z + cc.w * wb.w;
        #pragma unroll
        for (int off = 16; off > 0; off >>= 1)
            s += __shfl_xor_sync(0xffffffffu, s, off);
        if (lane == 0) {
            score_s[r] = s;
            g_scores[b * LL + c * 32 + r] = s;
        }
    }
    __syncthreads();

    if (t < 32) {
        float m = score_s[t];
        #pragma unroll
        for (int off = 16; off > 0; off >>= 1)
            m = fmaxf(m, __shfl_xor_sync(0xffffffffu, m, off));
        if (lane == 0) mred_s[0] = m;
        __syncwarp();
        float m_c = mred_s[0];
        float e = expf(score_s[t] - m_c);
        esc_s[t] = e;
        float sum = e;
        #pragma unroll
        for (int off = 16; off > 0; off >>= 1)
            sum += __shfl_xor_sync(0xffffffffu, sum, off);
        if (lane == 0) { g_ms[b * NCH + c] = m_c; g_Ss[b * NCH + c] = sum; }
    }
    __syncthreads();

    float a0 = 0, a1 = 0, a2 = 0, a3 = 0;
    #pragma unroll
    for (int l = 0; l < 32; l += 4) {
        a0 = fmaf(esc_s[l + 0], es[(l + 0) * 256 + t], a0);
        a1 = fmaf(esc_s[l + 1], es[(l + 1) * 256 + t], a1);
        a2 = fmaf(esc_s[l + 2], es[(l + 2) * 256 + t], a2);
        a3 = fmaf(esc_s[l + 3], es[(l + 3) * 256 + t], a3);
    }
    g_part[((size_t)b * NCH + c) * 256 + t] = (a0 + a1) + (a2 + a3);
}

// ================= K2: mega — kB + gates + lstm + logits ====================
// Phase safety: all flag-setters are low block-ids (wave-1 resident at occ>=2,
// enforced by __launch_bounds__(256,3)); waiters never gate setters.
__global__ void __launch_bounds__(256, 3) k_mega(
    const float* __restrict__ tokens_f,     // actually int*, cast below
    const float* __restrict__ emb_table,
    const float* __restrict__ hidden,
    const float* __restrict__ cell,
    const float* __restrict__ W_ih, const float* __restrict__ b_ih,
    const float* __restrict__ W_hh, const float* __restrict__ b_hh,
    const float* __restrict__ Wo,  const float* __restrict__ bo,
    float* __restrict__ out) {
    __shared__ __align__(16) char sarena[47744];
    int bid = blockIdx.x;
    int t = threadIdx.x;

    // ---------- phase 1: kB (blocks 0..31) ----------
    if (bid < 32) {
        float* mc_s    = (float*)sarena;            // [NCH]
        float* Ss_s    = mc_s + NCH;
        float* mred    = Ss_s + NCH;
        float* scale_s = mred + NCH;
        float* stat_s  = scale_s + NCH;             // [2]
        int b = bid;
        const int* tokens = (const int*)tokens_f;

        int tok = tokens[b];
        g_xT[t * 32 + b] = emb_table[(long long)tok * HH + t];
        g_xT[(512 + t) * 32 + b] = hidden[b * HH + t];

        if (t < NCH) {
            mc_s[t] = g_ms[b * NCH + t];
            Ss_s[t] = g_Ss[b * NCH + t];
            mred[t] = mc_s[t];
        }
        __syncthreads();
        for (int off = NCH / 2; off > 0; off >>= 1) {
            if (t < off) mred[t] = fmaxf(mred[t], mred[t + off]);
            __syncthreads();
        }
        float m = mred[0];
        if (t < NCH) {
            float e = expf(mc_s[t] - m);
            scale_s[t] = e;
            mred[t] = Ss_s[t] * e;
        }
        __syncthreads();
        for (int off = NCH / 2; off > 0; off >>= 1) {
            if (t < off) mred[t] += mred[t + off];
            __syncthreads();
        }
        float invZ = 1.0f / mred[0];
        if (t == 0) { stat_s[0] = m; stat_s[1] = invZ; }
        if (t < NCH) scale_s[t] *= invZ;
        __syncthreads();

        float s0 = 0, s1 = 0, s2 = 0, s3 = 0;
        #pragma unroll
        for (int c = 0; c < NCH; c += 4) {
            s0 = fmaf(g_part[((size_t)b * NCH + c + 0) * 256 + t], scale_s[c + 0], s0);
            s1 = fmaf(g_part[((size_t)b * NCH + c + 1) * 256 + t], scale_s[c + 1], s1);
            s2 = fmaf(g_part[((size_t)b * NCH + c + 2) * 256 + t], scale_s[c + 2], s2);
            s3 = fmaf(g_part[((size_t)b * NCH + c + 3) * 256 + t], scale_s[c + 3], s3);
        }
        float s = (s0 + s1) + (s2 + s3);
        g_x2[b * K2H + 256 + t] = s;
        g_xT[(256 + t) * 32 + b] = s;

        float mm = stat_s[0], iz = stat_s[1];
        const float4* sc4 = (const float4*)(g_scores + b * LL + t * 8);
        float4* o4 = (float4*)(out + OUT_AW + b * LL + t * 8);
        float4 v0 = sc4[0], v1 = sc4[1];
        float4 r0, r1;
        r0.x = expf(v0.x - mm) * iz; r0.y = expf(v0.y - mm) * iz;
        r0.z = expf(v0.z - mm) * iz; r0.w = expf(v0.w - mm) * iz;
        r1.x = expf(v1.x - mm) * iz; r1.y = expf(v1.y - mm) * iz;
        r1.z = expf(v1.z - mm) * iz; r1.w = expf(v1.w - mm) * iz;
        o4[0] = r0; o4[1] = r1;
        __syncthreads();
        if (t == 0) arrive(&g_f1);
    }

    // ---------- phase 2: gates (blocks 0..255) ----------
    if (bid < 256) {
        spin_ge(&g_f1, 32, t);
        float* Ws = (float*)sarena;      // [GT*KT]
        float* xs = Ws + GT * KT;        // [KT*32]
        int g0 = (bid & 31) * GT;
        int ks = bid >> 5;
        int klo = ks * KT;

        #pragma unroll
        for (int i = 0; i < GT * KT / 256; i++) {
            int idx = t + i * 256;
            int g = idx / KT, kk = idx - g * KT;
            int kg = klo + kk;
            float v = (kg < 512) ? W_ih[(size_t)(g0 + g) * 512 + kg]
                                 : W_hh[(size_t)(g0 + g) * 256 + (kg - 512)];
            Ws[g * KT + kk] = v;
        }
        #pragma unroll
        for (int i = 0; i < KT * 32 / 256; i++) {
            int idx = t + i * 256;
            xs[idx] = g_xT[klo * 32 + idx];
        }
        __syncthreads();

        int lane = t & 31, w = t >> 5;
        int gl = w * 4;
        float acc[4] = {0, 0, 0, 0};
        #pragma unroll 4
        for (int kk = 0; kk < KT; kk += 2) {
            float x0 = xs[kk * 32 + lane];
            float x1 = xs[(kk + 1) * 32 + lane];
            #pragma unroll
            for (int g = 0; g < 4; g++) {
                float2 wp = *(const float2*)&Ws[(gl + g) * KT + kk];
                acc[g] = fmaf(wp.x, x0, fmaf(wp.y, x1, acc[g]));
            }
        }
        float* gp = g_gpart + ks * 32768;
        #pragma unroll
        for (int g = 0; g < 4; g++) {
            float a = acc[g];
            int gr = g0 + gl + g;
            if (ks == 0) a += b_ih[gr] + b_hh[gr];
            gp[gr * 32 + lane] = a;
        }
        __syncthreads();          // arena reuse barrier
        if (t == 0) arrive(&g_f2);
    }

    // ---------- phase 3: lstm (blocks 0..31) ----------
    if (bid < 32) {
        spin_ge(&g_f2, 256, t);
        int b = bid, h = t;
        float ig = 0, fg = 0, gg = 0, og = 0;
        #pragma unroll
        for (int ks = 0; ks < NKS; ks++) {
            const float* gp = g_gpart + ks * 32768;
            ig += gp[(0 * HH + h) * 32 + b];
            fg += gp[(1 * HH + h) * 32 + b];
            gg += gp[(2 * HH + h) * 32 + b];
            og += gp[(3 * HH + h) * 32 + b];
        }
        float c_new = sigf(fg) * cell[b * HH + h] + sigf(ig) * tanhf(gg);
        float h_new = sigf(og) * tanhf(c_new);
        out[OUT_H + b * HH + h] = h_new;
        out[OUT_C + b * HH + h] = c_new;
        g_x2[b * K2H + h] = h_new;
        __syncthreads();
        if (t == 0) arrive(&g_f3);
    }

    // ---------- phase 4: logits GEMM (all 393 blocks) ----------
    {
        float* WtP  = (float*)sarena;                 // [2][128*WSD]
        float* XsP  = (float*)(sarena + 34816);       // [2][32*WSD+8]
        float* red  = (float*)(sarena + 34816 + 8768);// [1024]
        int v0 = bid * 128;
        int vq = t >> 3, bq = t & 7;

        float4 wreg[4];
        float4 xreg;

        auto loadW = [&](int kt) {
            #pragma unroll
            for (int jj = 0; jj < 4; jj++) {
                int idx = jj * 256 + t;
                int row = idx >> 3, q = idx & 7;
                int vr = v0 + row;
                wreg[jj] = (vr < VV) ? *(const float4*)(Wo + (size_t)vr * 512 + kt + 4 * q)
                                     : make_float4(0.f, 0.f, 0.f, 0.f);
            }
        };
        auto loadX = [&](int kt) {
            xreg = *(const float4*)(g_x2 + (t >> 3) * K2H + kt + 4 * (t & 7));
        };
        auto storeW = [&](int s) {
            float* W = WtP + s * (128 * WSD);
            #pragma unroll
            for (int jj = 0; jj < 4; jj++) {
                int idx = jj * 256 + t;
                int row = idx >> 3, q = idx & 7;
                float* p = &W[row * WSD + 4 * q];
                *(float2*)(p)     = make_float2(wreg[jj].x, wreg[jj].y);
                *(float2*)(p + 2) = make_float2(wreg[jj].z, wreg[jj].w);
            }
        };
        auto storeX = [&](int s) {
            float* X = XsP + s * (32 * WSD + 8);
            int b = t >> 3, q = t & 7;
            float* p = &X[b * WSD + 4 * q + 2 * ((b >> 4) & 1)];
            *(float2*)(p)     = make_float2(xreg.x, xreg.y);
            *(float2*)(p + 2) = make_float2(xreg.z, xreg.w);
        };

        // prefetch W tile 0 (g_x2-independent) before waiting for lstm
        loadW(0);
        storeW(0);
        spin_ge(&g_f3, 32, t);
        loadX(0);
        storeX(0);

        unsigned long long acc[4][4];
        #pragma unroll
        for (int i = 0; i < 4; i++)
            #pragma unroll
            for (int j = 0; j < 4; j++) acc[i][j] = 0ull;
        __syncthreads();

        for (int it = 0; it < 16; it++) {
            int cur = it & 1;
            if (it < 15) { loadW((it + 1) * 32); loadX((it + 1) * 32); }
            const float* W = WtP + cur * (128 * WSD);
            const float* X = XsP + cur * (32 * WSD + 8);
            #pragma unroll
            for (int kk = 0; kk < 32; kk += 2) {
                unsigned long long wv[4], xv[4];
                #pragma unroll
                for (int i = 0; i < 4; i++)
                    wv[i] = *(const unsigned long long*)(W + (vq * 4 + i) * WSD + kk);
                #pragma unroll
                for (int j = 0; j < 4; j++) {
                    int bj = bq * 4 + j;
                    xv[j] = *(const unsigned long long*)(X + bj * WSD + kk + 2 * ((bj >> 4) & 1));
                }
                #pragma unroll
                for (int i = 0; i < 4; i++)
                    #pragma unroll
                    for (int j = 0; j < 4; j++)
                        acc[i][j] = ffma2(wv[i], xv[j], acc[i][j]);
            }
            if (it < 15) { storeW(cur ^ 1); storeX(cur ^ 1); }
            __syncthreads();
        }

        float lg[4][4];
        float lmax[4] = { -1e30f, -1e30f, -1e30f, -1e30f };
        #pragma unroll
        for (int i = 0; i < 4; i++) {
            int vv = v0 + vq * 4 + i;
            if (vv < VV) {
                float bias = bo[vv];
                #pragma unroll
                for (int j = 0; j < 4; j++) {
                    float lo = __uint_as_float((unsigned)(acc[i][j] & 0xffffffffull));
                    float hi = __uint_as_float((unsigned)(acc[i][j] >> 32));
                    float l = (lo + hi) + bias;
                    lg[i][j] = l;
                    lmax[j] = fmaxf(lmax[j], l);
                    out[(size_t)(bq * 4 + j) * VV + vv] = l;
                }
            } else {
                #pragma unroll
                for (int j = 0; j < 4; j++) lg[i][j] = -1e30f;
            }
        }

        #pragma unroll
        for (int j = 0; j < 4; j++) red[vq * 32 + bq * 4 + j] = lmax[j];
        __syncthreads();
        for (int off = 16; off > 0; off >>= 1) {
            if (vq < off) {
                #pragma unroll
                for (int j = 0; j < 4; j++) {
                    int b = bq * 4 + j;
                    red[vq * 32 + b] = fmaxf(red[vq * 32 + b], red[(vq + off) * 32 + b]);
                }
            }
            __syncthreads();
        }
        float mb[4];
        #pragma unroll
        for (int j = 0; j < 4; j++) mb[j] = red[bq * 4 + j];
        __syncthreads();

        float lsum[4] = { 0.f, 0.f, 0.f, 0.f };
        #pragma unroll
        for (int i = 0; i < 4; i++)
            #pragma unroll
            for (int j = 0; j < 4; j++)
                if (lg[i][j] > -1e29f) lsum[j] += expf(lg[i][j] - mb[j]);
        #pragma unroll
        for (int j = 0; j < 4; j++) red[vq * 32 + bq * 4 + j] = lsum[j];
        __syncthreads();
        for (int off = 16; off > 0; off >>= 1) {
            if (vq < off) {
                #pragma unroll
                for (int j = 0; j < 4; j++) {
                    int b = bq * 4 + j;
                    red[vq * 32 + b] += red[(vq + off) * 32 + b];
                }
            }
            __syncthreads();
        }
        if (vq == 0) {
            #pragma unroll
            for (int j = 0; j < 4; j++) {
                int b = bq * 4 + j;
                g_lsem[bid * 32 + b] = mb[j];
                g_lses[bid * 32 + b] = red[b];
            }
        }
    }
}

// ================= K3: lse-merge + subtract + flag reset ====================
__global__ void k_sub(float* __restrict__ out) {
    __shared__ float lse_s[2];
    const int NF4 = (BB * VV) / 4;        // 402056
    int t = threadIdx.x;
    int e_start = blockIdx.x * 4096;
    int b_lo = e_start / VV;
    int e_last = min(e_start + 4095, BB * VV - 1);
    int b_hi = e_last / VV;

    int w = t >> 5;
    if (w < 2) {
        int b = (w == 0) ? b_lo : b_hi;
        int lane = t & 31;
        float m = -1e30f, S = 0.f;
        for (int i = lane; i < NBLK; i += 32) {
            float m2 = g_lsem[i * 32 + b];
            float S2 = g_lses[i * 32 + b];
            float mm = fmaxf(m, m2);
            S = S * expf(m - mm) + S2 * expf(m2 - mm);
            m = mm;
        }
        #pragma unroll
        for (int off = 16; off > 0; off >>= 1) {
            float m2 = __shfl_xor_sync(0xffffffffu, m, off);
            float S2 = __shfl_xor_sync(0xffffffffu, S, off);
            float mm = fmaxf(m, m2);
            S = S * expf(m - mm) + S2 * expf(m2 - mm);
            m = mm;
        }
        if (lane == 0) lse_s[w] = m + logf(S);
    }
    // reset phase flags for the next graph replay (no one reads them in k_sub)
    if (blockIdx.x == 0 && t == 0) {
        g_fW = 0; g_f1 = 0; g_f2 = 0; g_f3 = 0;
    }
    __syncthreads();

    float l_lo = lse_s[0], l_hi = lse_s[1];
    int base = blockIdx.x * 1024 + t;
    float4* o4 = (float4*)out;
    #pragma unroll
    for (int j = 0; j < 4; j++) {
        int f = base + j * 256;
        if (f < NF4) {
            int e0 = f * 4;
            int b0 = e0 / VV;
            int bnd = (b0 + 1) * VV;
            float l0 = (b0 == b_lo) ? l_lo : l_hi;
            float l1 = l_hi;
            float4 v = o4[f];
            v.x -= (e0 + 0 >= bnd) ? l1 : l0;
            v.y -= (e0 + 1 >= bnd) ? l1 : l0;
            v.z -= (e0 + 2 >= bnd) ? l1 : l0;
            v.w -= (e0 + 3 >= bnd) ? l1 : l0;
            o4[f] = v;
        }
    }
}

extern "C" void kernel_launch(void* const* d_in, const int* in_sizes, int n_in,
                              void* d_out, int out_size) {
    const float* tokens_f  = (const float*)d_in[0];   // int*, cast inside kernel
    const float* hidden    = (const float*)d_in[1];
    const float* cell      = (const float*)d_in[2];
    const float* enc       = (const float*)d_in[3];
    const float* emb_table = (const float*)d_in[4];
    const float* W_attn    = (const float*)d_in[5];
    // d_in[6] = b_attn unused (softmax shift-invariance)
    const float* vvec      = (const float*)d_in[7];
    const float* W_ih      = (const float*)d_in[8];
    const float* b_ih      = (const float*)d_in[9];
    const float* W_hh      = (const float*)d_in[10];
    const float* b_hh      = (const float*)d_in[11];
    const float* W_out     = (const float*)d_in[12];
    const float* b_out     = (const float*)d_in[13];
    float* out = (float*)d_out;

    {
        dim3 g(NCH, BB);
        kA<<<g, 256>>>(enc, W_attn, vvec);                               // 1
    }
    k_mega<<<NBLK, 256>>>(tokens_f, emb_table, hidden, cell,
                          W_ih, b_ih, W_hh, b_hh, W_out, b_out, out);    // 2
    {
        const int NF4 = (BB * VV) / 4;
        k_sub<<<(NF4 + 1023) / 1024, 256>>>(out);                        // 3
    }
}

// round 14
// speedup vs baseline: 1.4428x; 1.4428x over previous
#include <cuda_runtime.h>
#include <math.h>

#define BB 32
#define HH 256
#define LL 2048
#define VV 50257
#define K2H 512
#define NBLK 393          // ceil(VV/128)
#define NKS 8             // k-splits for gates
#define NCH 64            // attention l-chunks (32 rows each)
#define NCJ 4             // chunks per kA block

// d_out layout: log_probs[B*V], h_new[B*H], c_new[B*H], attn_weights[B*L]
#define OUT_H  (BB * VV)
#define OUT_C  (OUT_H + BB * HH)
#define OUT_AW (OUT_C + BB * HH)

// ---------------- scratch ----------------
__device__ __align__(16) float g_wpart[4 * 256];        // partial We^T v
__device__ __align__(16) float g_scores[BB * LL];
__device__ __align__(16) float g_ms[BB * NCH];          // per-chunk max
__device__ __align__(16) float g_Ss[BB * NCH];          // per-chunk expsum
__device__ __align__(16) float g_part[BB * NCH * HH];   // per-chunk weighted partials
__device__ __align__(16) float g_xT[768 * 32];          // [k][b] LSTM input transposed
__device__ __align__(16) float g_gpart[NKS * 1024 * 32];// gate partials [ks][g][b]
__device__ __align__(16) float g_x2[BB * K2H];          // concat(h_new, attnap) per b
__device__ __align__(16) float g_lsem[NBLK * 32];       // per-vblock max per b
__device__ __align__(16) float g_lses[NBLK * 32];       // per-vblock expsum per b
__device__ float g_lse[BB];

static __device__ __forceinline__ unsigned long long ffma2(
    unsigned long long a, unsigned long long b, unsigned long long c) {
    unsigned long long d;
    asm("fma.rn.f32x2 %0, %1, %2, %3;" : "=l"(d) : "l"(a), "l"(b), "l"(c));
    return d;
}

static __device__ __forceinline__ float sigf(float x) { return 1.0f / (1.0f + expf(-x)); }

// ---------------- K1: w partials only (4 blocks) ----------------
__global__ void k_init(const float* __restrict__ W_attn, const float* __restrict__ vvec) {
    int t = threadIdx.x;
    int kb = blockIdx.x * 64;
    float a0 = 0, a1 = 0, a2 = 0, a3 = 0;
    #pragma unroll 4
    for (int i = 0; i < 64; i += 4) {
        a0 = fmaf(vvec[kb + i + 0], W_attn[(kb + i + 0) * 512 + 256 + t], a0);
        a1 = fmaf(vvec[kb + i + 1], W_attn[(kb + i + 1) * 512 + 256 + t], a1);
        a2 = fmaf(vvec[kb + i + 2], W_attn[(kb + i + 2) * 512 + 256 + t], a2);
        a3 = fmaf(vvec[kb + i + 3], W_attn[(kb + i + 3) * 512 + 256 + t], a3);
    }
    g_wpart[blockIdx.x * 256 + t] = (a0 + a1) + (a2 + a3);
}

// ---------------- K2: attention pass 1 — register-staged, score-fused, pipelined -------
// Block (cg, b) processes chunks cg*4 .. cg*4+3 (32 rows each).
// Warp w owns rows 4w..4w+3; lane loads 2 float4 per row into registers (MLP=8),
// computes row scores directly from regs, STS into double-buffered smem tile,
// prefetches next chunk during softmax/weighted phases.
__global__ void __launch_bounds__(256) kA(const float* __restrict__ enc) {
    extern __shared__ float dyn[];
    float* esb[2] = { dyn, dyn + 8192 };        // 2 x 32 KB tiles
    float* w_s     = dyn + 16384;               // [256]
    float* score_s = w_s + 256;                 // [32]
    float* esc_s   = score_s + 32;              // [32]
    float* mred_s  = esc_s + 32;                // [1]

    int cg = blockIdx.x, b = blockIdx.y;
    int t = threadIdx.x;
    int lane = t & 31, w = t >> 5;

    w_s[t] = g_wpart[t] + g_wpart[256 + t] + g_wpart[512 + t] + g_wpart[768 + t];

    // prologue: load chunk 0 rows into registers (8 independent LDG.128)
    float4 va[4], vb[4];
    {
        const float4* base = (const float4*)(enc + ((size_t)b * LL + cg * NCJ * 32) * HH);
        #pragma unroll
        for (int i = 0; i < 4; i++) {
            int r = w * 4 + i;
            va[i] = base[r * 64 + lane];
            vb[i] = base[r * 64 + 32 + lane];
        }
    }
    __syncthreads();     // w_s ready
    float4 wa = ((const float4*)w_s)[lane];
    float4 wb = ((const float4*)w_s)[32 + lane];

    for (int j = 0; j < NCJ; j++) {
        int p = j & 1;
        int c = cg * NCJ + j;
        float* es = esb[p];

        // scores from registers + stage to smem
        #pragma unroll
        for (int i = 0; i < 4; i++) {
            int r = w * 4 + i;
            float s = va[i].x * wa.x + va[i].y * wa.y + va[i].z * wa.z + va[i].w * wa.w
                    + vb[i].x * wb.x + vb[i].y * wb.y + vb[i].z * wb.z + vb[i].w * wb.w;
            #pragma unroll
            for (int off = 16; off > 0; off >>= 1)
                s += __shfl_xor_sync(0xffffffffu, s, off);
            if (lane == 0) {
                score_s[r] = s;
                g_scores[b * LL + c * 32 + r] = s;
            }
            ((float4*)(es + r * 256))[lane] = va[i];
            ((float4*)(es + r * 256))[32 + lane] = vb[i];
        }
        __syncthreads();

        // prefetch next chunk into the just-freed registers (overlaps phases below)
        if (j + 1 < NCJ) {
            const float4* nb = (const float4*)(enc + ((size_t)b * LL + (c + 1) * 32) * HH);
            #pragma unroll
            for (int i = 0; i < 4; i++) {
                int r = w * 4 + i;
                va[i] = nb[r * 64 + lane];
                vb[i] = nb[r * 64 + 32 + lane];
            }
        }

        // chunk softmax stats (warp 0)
        if (t < 32) {
            float m = score_s[t];
            #pragma unroll
            for (int off = 16; off > 0; off >>= 1)
                m = fmaxf(m, __shfl_xor_sync(0xffffffffu, m, off));
            if (lane == 0) mred_s[0] = m;
            __syncwarp();
            float m_c = mred_s[0];
            float e = expf(score_s[t] - m_c);
            esc_s[t] = e;
            float sum = e;
            #pragma unroll
            for (int off = 16; off > 0; off >>= 1)
                sum += __shfl_xor_sync(0xffffffffu, sum, off);
            if (lane == 0) { g_ms[b * NCH + c] = m_c; g_Ss[b * NCH + c] = sum; }
        }
        __syncthreads();

        // weighted partial sums: thread = h
        float a0 = 0, a1 = 0, a2 = 0, a3 = 0;
        #pragma unroll
        for (int l = 0; l < 32; l += 4) {
            a0 = fmaf(esc_s[l + 0], es[(l + 0) * 256 + t], a0);
            a1 = fmaf(esc_s[l + 1], es[(l + 1) * 256 + t], a1);
            a2 = fmaf(esc_s[l + 2], es[(l + 2) * 256 + t], a2);
            a3 = fmaf(esc_s[l + 3], es[(l + 3) * 256 + t], a3);
        }
        g_part[((size_t)b * NCH + c) * 256 + t] = (a0 + a1) + (a2 + a3);
        // next iteration's STS targets the other buffer; its leading __syncthreads
        // orders score_s/esc_s reuse.
    }
}

// ---------------- K3: attention combine + emb/hidden transpose ----------------
__global__ void kB(float* __restrict__ out,
                   const int* __restrict__ tokens,
                   const float* __restrict__ emb_table,
                   const float* __restrict__ hidden) {
    __shared__ float mc_s[NCH], Ss_s[NCH], mred[NCH], scale_s[NCH];
    __shared__ float stat_s[2];
    int b = blockIdx.x, t = threadIdx.x;

    int tok = tokens[b];
    g_xT[t * 32 + b] = emb_table[(long long)tok * HH + t];
    g_xT[(512 + t) * 32 + b] = hidden[b * HH + t];

    if (t < NCH) {
        mc_s[t] = g_ms[b * NCH + t];
        Ss_s[t] = g_Ss[b * NCH + t];
        mred[t] = mc_s[t];
    }
    __syncthreads();
    for (int off = NCH / 2; off > 0; off >>= 1) {
        if (t < off) mred[t] = fmaxf(mred[t], mred[t + off]);
        __syncthreads();
    }
    float m = mred[0];
    if (t < NCH) {
        float e = expf(mc_s[t] - m);
        scale_s[t] = e;
        mred[t] = Ss_s[t] * e;
    }
    __syncthreads();
    for (int off = NCH / 2; off > 0; off >>= 1) {
        if (t < off) mred[t] += mred[t + off];
        __syncthreads();
    }
    float invZ = 1.0f / mred[0];
    if (t == 0) { stat_s[0] = m; stat_s[1] = invZ; }
    if (t < NCH) scale_s[t] *= invZ;
    __syncthreads();

    float s0 = 0, s1 = 0, s2 = 0, s3 = 0;
    #pragma unroll
    for (int c = 0; c < NCH; c += 4) {
        s0 = fmaf(g_part[((size_t)b * NCH + c + 0) * 256 + t], scale_s[c + 0], s0);
        s1 = fmaf(g_part[((size_t)b * NCH + c + 1) * 256 + t], scale_s[c + 1], s1);
        s2 = fmaf(g_part[((size_t)b * NCH + c + 2) * 256 + t], scale_s[c + 2], s2);
        s3 = fmaf(g_part[((size_t)b * NCH + c + 3) * 256 + t], scale_s[c + 3], s3);
    }
    float s = (s0 + s1) + (s2 + s3);
    g_x2[b * K2H + 256 + t] = s;
    g_xT[(256 + t) * 32 + b] = s;

    float mm = stat_s[0], iz = stat_s[1];
    const float4* sc4 = (const float4*)(g_scores + b * LL + t * 8);
    float4* o4 = (float4*)(out + OUT_AW + b * LL + t * 8);
    float4 v0 = sc4[0], v1 = sc4[1];
    float4 r0, r1;
    r0.x = expf(v0.x - mm) * iz; r0.y = expf(v0.y - mm) * iz;
    r0.z = expf(v0.z - mm) * iz; r0.w = expf(v0.w - mm) * iz;
    r1.x = expf(v1.x - mm) * iz; r1.y = expf(v1.y - mm) * iz;
    r1.z = expf(v1.z - mm) * iz; r1.w = expf(v1.w - mm) * iz;
    o4[0] = r0; o4[1] = r1;
}

// ---------------- K4: LSTM gates GEMM — smem-tiled, 256 blocks ----------------
#define GT 32
#define KT 96
__global__ void k_gates(const float* __restrict__ W_ih, const float* __restrict__ b_ih,
                        const float* __restrict__ W_hh, const float* __restrict__ b_hh) {
    __shared__ float Ws[GT * KT];   // 12 KB  [g][k]
    __shared__ float xs[KT * 32];   // 12 KB  [k][b]
    int t = threadIdx.x;
    int g0 = blockIdx.x * GT;
    int ks = blockIdx.y;
    int klo = ks * KT;

    #pragma unroll
    for (int i = 0; i < GT * KT / 256; i++) {
        int idx = t + i * 256;
        int g = idx / KT, kk = idx - g * KT;
        int kg = klo + kk;
        float v = (kg < 512) ? W_ih[(size_t)(g0 + g) * 512 + kg]
                             : W_hh[(size_t)(g0 + g) * 256 + (kg - 512)];
        Ws[g * KT + kk] = v;
    }
    #pragma unroll
    for (int i = 0; i < KT * 32 / 256; i++) {
        int idx = t + i * 256;
        xs[idx] = g_xT[klo * 32 + idx];
    }
    __syncthreads();

    int lane = t & 31, w = t >> 5;
    int gl = w * 4;
    float acc[4] = {0, 0, 0, 0};
    #pragma unroll 4
    for (int kk = 0; kk < KT; kk += 2) {
        float x0 = xs[kk * 32 + lane];
        float x1 = xs[(kk + 1) * 32 + lane];
        #pragma unroll
        for (int g = 0; g < 4; g++) {
            float2 wp = *(const float2*)&Ws[(gl + g) * KT + kk];
            acc[g] = fmaf(wp.x, x0, fmaf(wp.y, x1, acc[g]));
        }
    }
    float* gp = g_gpart + ks * 32768;
    #pragma unroll
    for (int g = 0; g < 4; g++) {
        float a = acc[g];
        int gr = g0 + gl + g;
        if (ks == 0) a += b_ih[gr] + b_hh[gr];
        gp[gr * 32 + lane] = a;
    }
}

// ---------------- K5: LSTM pointwise (sums 8 k-split partials) ----------------
__global__ void k_lstm(const float* __restrict__ cell, float* __restrict__ out) {
    int b = blockIdx.x, h = threadIdx.x;
    float ig = 0, fg = 0, gg = 0, og = 0;
    #pragma unroll
    for (int ks = 0; ks < NKS; ks++) {
        const float* gp = g_gpart + ks * 32768;
        ig += gp[(0 * HH + h) * 32 + b];
        fg += gp[(1 * HH + h) * 32 + b];
        gg += gp[(2 * HH + h) * 32 + b];
        og += gp[(3 * HH + h) * 32 + b];
    }
    float c_new = sigf(fg) * cell[b * HH + h] + sigf(ig) * tanhf(gg);
    float h_new = sigf(og) * tanhf(c_new);
    out[OUT_H + b * HH + h] = h_new;
    out[OUT_C + b * HH + h] = c_new;
    g_x2[b * K2H + h] = h_new;
}

// ---------------- K6: logits GEMM — f32x2 packed over even/odd k, 3 blocks/SM ----------
#define WSD 34
__global__ void __launch_bounds__(256, 3) k_logits(const float* __restrict__ Wo,
                                                   const float* __restrict__ bo,
                                                   float* __restrict__ out) {
    __shared__ float Wt[2][128 * WSD];
    __shared__ float Xs[2][32 * WSD + 8];
    __shared__ float red[32 * 32];        // [vq][b] reduction scratch

    int t = threadIdx.x;
    int v0 = blockIdx.x * 128;
    int vq = t >> 3, bq = t & 7;

    float4 wreg[4];
    float4 xreg;

    auto load_tile = [&](int kt) {
        #pragma unroll
        for (int jj = 0; jj < 4; jj++) {
            int idx = jj * 256 + t;
            int row = idx >> 3, q = idx & 7;
            int vr = v0 + row;
            wreg[jj] = (vr < VV) ? *(const float4*)(Wo + (size_t)vr * 512 + kt + 4 * q)
                                 : make_float4(0.f, 0.f, 0.f, 0.f);
        }
        xreg = *(const float4*)(g_x2 + (t >> 3) * K2H + kt + 4 * (t & 7));
    };
    auto store_tile = [&](int s) {
        #pragma unroll
        for (int jj = 0; jj < 4; jj++) {
            int idx = jj * 256 + t;
            int row = idx >> 3, q = idx & 7;
            float* p = &Wt[s][row * WSD + 4 * q];
            *(float2*)(p)     = make_float2(wreg[jj].x, wreg[jj].y);
            *(float2*)(p + 2) = make_float2(wreg[jj].z, wreg[jj].w);
        }
        int b = t >> 3, q = t & 7;
        float* p = &Xs[s][b * WSD + 4 * q + 2 * ((b >> 4) & 1)];
        *(float2*)(p)     = make_float2(xreg.x, xreg.y);
        *(float2*)(p + 2) = make_float2(xreg.z, xreg.w);
    };

    unsigned long long acc[4][4];
    #pragma unroll
    for (int i = 0; i < 4; i++)
        #pragma unroll
        for (int j = 0; j < 4; j++) acc[i][j] = 0ull;

    load_tile(0);
    store_tile(0);
    __syncthreads();

    for (int it = 0; it < 16; it++) {
        int cur = it & 1;
        if (it < 15) load_tile((it + 1) * 32);
        const float* W = Wt[cur];
        const float* X = Xs[cur];
        #pragma unroll
        for (int kk = 0; kk < 32; kk += 2) {
            unsigned long long wv[4], xv[4];
            #pragma unroll
            for (int i = 0; i < 4; i++)
                wv[i] = *(const unsigned long long*)(W + (vq * 4 + i) * WSD + kk);
            #pragma unroll
            for (int j = 0; j < 4; j++) {
                int bj = bq * 4 + j;
                xv[j] = *(const unsigned long long*)(X + bj * WSD + kk + 2 * ((bj >> 4) & 1));
            }
            #pragma unroll
            for (int i = 0; i < 4; i++)
                #pragma unroll
                for (int j = 0; j < 4; j++)
                    acc[i][j] = ffma2(wv[i], xv[j], acc[i][j]);
        }
        if (it < 15) store_tile(cur ^ 1);
        __syncthreads();
    }

    float lg[4][4];
    float lmax[4] = { -1e30f, -1e30f, -1e30f, -1e30f };
    #pragma unroll
    for (int i = 0; i < 4; i++) {
        int vv = v0 + vq * 4 + i;
        if (vv < VV) {
            float bias = bo[vv];
            #pragma unroll
            for (int j = 0; j < 4; j++) {
                float lo = __uint_as_float((unsigned)(acc[i][j] & 0xffffffffull));
                float hi = __uint_as_float((unsigned)(acc[i][j] >> 32));
                float l = (lo + hi) + bias;
                lg[i][j] = l;
                lmax[j] = fmaxf(lmax[j], l);
                out[(size_t)(bq * 4 + j) * VV + vv] = l;
            }
        } else {
            #pragma unroll
            for (int j = 0; j < 4; j++) lg[i][j] = -1e30f;
        }
    }

    #pragma unroll
    for (int j = 0; j < 4; j++) red[vq * 32 + bq * 4 + j] = lmax[j];
    __syncthreads();
    for (int off = 16; off > 0; off >>= 1) {
        if (vq < off) {
            #pragma unroll
            for (int j = 0; j < 4; j++) {
                int b = bq * 4 + j;
                red[vq * 32 + b] = fmaxf(red[vq * 32 + b], red[(vq + off) * 32 + b]);
            }
        }
        __syncthreads();
    }
    float mb[4];
    #pragma unroll
    for (int j = 0; j < 4; j++) mb[j] = red[bq * 4 + j];
    __syncthreads();

    float lsum[4] = { 0.f, 0.f, 0.f, 0.f };
    #pragma unroll
    for (int i = 0; i < 4; i++)
        #pragma unroll
        for (int j = 0; j < 4; j++)
            if (lg[i][j] > -1e29f) lsum[j] += expf(lg[i][j] - mb[j]);
    #pragma unroll
    for (int j = 0; j < 4; j++) red[vq * 32 + bq * 4 + j] = lsum[j];
    __syncthreads();
    for (int off = 16; off > 0; off >>= 1) {
        if (vq < off) {
            #pragma unroll
            for (int j = 0; j < 4; j++) {
                int b = bq * 4 + j;
                red[vq * 32 + b] += red[(vq + off) * 32 + b];
            }
        }
        __syncthreads();
    }
    if (vq == 0) {
        #pragma unroll
        for (int j = 0; j < 4; j++) {
            int b = bq * 4 + j;
            g_lsem[blockIdx.x * 32 + b] = mb[j];
            g_lses[blockIdx.x * 32 + b] = red[b];
        }
    }
}

// ---------------- K7: merge per-block LSE partials ----------------
__global__ void k_lse() {
    __shared__ float mred[512], sred[512];
    int b = blockIdx.x, t = threadIdx.x;
    float m = -1e30f, S = 0.f;
    if (t < NBLK) {
        m = g_lsem[t * 32 + b];
        S = g_lses[t * 32 + b];
    }
    mred[t] = m; sred[t] = S;
    __syncthreads();
    for (int off = 256; off > 0; off >>= 1) {
        if (t < off) {
            float m1 = mred[t], m2 = mred[t + off];
            float s1 = sred[t], s2 = sred[t + off];
            float mm = fmaxf(m1, m2);
            mred[t] = mm;
            sred[t] = s1 * expf(m1 - mm) + s2 * expf(m2 - mm);
        }
        __syncthreads();
    }
    if (t == 0) g_lse[b] = mred[0] + logf(sred[0]);
}

// ---------------- K8: log_probs -= lse, flat float4 (B*V divisible by 4) ----------------
__global__ void k_sub(float* __restrict__ out) {
    const int NF4 = (BB * VV) / 4;        // 402056
    int base = blockIdx.x * 1024 + threadIdx.x;
    float4* o4 = (float4*)out;
    #pragma unroll
    for (int j = 0; j < 4; j++) {
        int f = base + j * 256;
        if (f < NF4) {
            int e0 = f * 4;
            int b0 = e0 / VV;
            int bnd = (b0 + 1) * VV;
            float l0 = g_lse[b0];
            float l1 = (b0 < BB - 1) ? g_lse[b0 + 1] : 0.f;
            float4 v = o4[f];
            v.x -= (e0 + 0 >= bnd) ? l1 : l0;
            v.y -= (e0 + 1 >= bnd) ? l1 : l0;
            v.z -= (e0 + 2 >= bnd) ? l1 : l0;
            v.w -= (e0 + 3 >= bnd) ? l1 : l0;
            o4[f] = v;
        }
    }
}

extern "C" void kernel_launch(void* const* d_in, const int* in_sizes, int n_in,
                              void* d_out, int out_size) {
    const int*   tokens    = (const int*)d_in[0];
    const float* hidden    = (const float*)d_in[1];
    const float* cell      = (const float*)d_in[2];
    const float* enc       = (const float*)d_in[3];
    const float* emb_table = (const float*)d_in[4];
    const float* W_attn    = (const float*)d_in[5];
    // d_in[6] = b_attn unused (softmax shift-invariance)
    const float* vvec      = (const float*)d_in[7];
    const float* W_ih      = (const float*)d_in[8];
    const float* b_ih      = (const float*)d_in[9];
    const float* W_hh      = (const float*)d_in[10];
    const float* b_hh      = (const float*)d_in[11];
    const float* W_out     = (const float*)d_in[12];
    const float* b_out     = (const float*)d_in[13];
    float* out = (float*)d_out;

    // Idempotent; not a stream op (not captured into the graph).
    cudaFuncSetAttribute(kA, cudaFuncAttributeMaxDynamicSharedMemorySize, 69632);

    k_init<<<4, 256>>>(W_attn, vvec);                                    // 1
    {
        dim3 g(NCH / NCJ, BB);
        kA<<<g, 256, 69632>>>(enc);                                      // 2
    }
    kB<<<BB, 256>>>(out, tokens, emb_table, hidden);                     // 3
    {
        dim3 g(1024 / GT, NKS);
        k_gates<<<g, 256>>>(W_ih, b_ih, W_hh, b_hh);                     // 4
    }
    k_lstm<<<BB, 256>>>(cell, out);                                      // 5
    k_logits<<<NBLK, 256>>>(W_out, b_out, out);                          // 6
    k_lse<<<BB, 512>>>();                                                // 7
    {
        const int NF4 = (BB * VV) / 4;
        k_sub<<<(NF4 + 1023) / 1024, 256>>>(out);                        // 8
    }
}

// round 16
// speedup vs baseline: 1.4982x; 1.0384x over previous
#include <cuda_runtime.h>
#include <math.h>

#define BB 32
#define HH 256
#define LL 2048
#define VV 50257
#define K2H 512
#define NBLK 393          // ceil(VV/128)
#define NKS 8             // k-splits for gates
#define NC2 32            // attnpart l-chunks (64 rows each)

// d_out layout: log_probs[B*V], h_new[B*H], c_new[B*H], attn_weights[B*L]
#define OUT_H  (BB * VV)
#define OUT_C  (OUT_H + BB * HH)
#define OUT_AW (OUT_C + BB * HH)

// ---------------- scratch ----------------
__device__ __align__(16) float g_wpart[4 * 256];        // partial We^T v
__device__ __align__(16) float g_scores[BB * LL];
__device__ __align__(16) float g_part[BB * NC2 * HH];   // per-chunk weighted partials
__device__ __align__(16) float g_xT[768 * 32];          // [k][b] LSTM input transposed
__device__ __align__(16) float g_gpart[NKS * 1024 * 32];// gate partials [ks][g][b]
__device__ __align__(16) float g_x2[BB * K2H];          // concat(h_new, attnap) per b
__device__ __align__(16) float g_lsem[NBLK * 32];       // per-vblock max per b
__device__ __align__(16) float g_lses[NBLK * 32];       // per-vblock expsum per b
__device__ float g_lse[BB];

static __device__ __forceinline__ unsigned long long ffma2(
    unsigned long long a, unsigned long long b, unsigned long long c) {
    unsigned long long d;
    asm("fma.rn.f32x2 %0, %1, %2, %3;" : "=l"(d) : "l"(a), "l"(b), "l"(c));
    return d;
}

static __device__ __forceinline__ float sigf(float x) { return 1.0f / (1.0f + expf(-x)); }

// ---------------- K1: w partials only (4 blocks) ----------------
__global__ void k_init(const float* __restrict__ W_attn, const float* __restrict__ vvec) {
    int t = threadIdx.x;
    int kb = blockIdx.x * 64;
    float a0 = 0, a1 = 0, a2 = 0, a3 = 0;
    #pragma unroll 4
    for (int i = 0; i < 64; i += 4) {
        a0 = fmaf(vvec[kb + i + 0], W_attn[(kb + i + 0) * 512 + 256 + t], a0);
        a1 = fmaf(vvec[kb + i + 1], W_attn[(kb + i + 1) * 512 + 256 + t], a1);
        a2 = fmaf(vvec[kb + i + 2], W_attn[(kb + i + 2) * 512 + 256 + t], a2);
        a3 = fmaf(vvec[kb + i + 3], W_attn[(kb + i + 3) * 512 + 256 + t], a3);
    }
    g_wpart[blockIdx.x * 256 + t] = (a0 + a1) + (a2 + a3);
}

// ---------------- K2: scores[b,l] = enc[b,l,:] . w — streaming GEMV ----------------
// 1024 blocks x 8 warps; warp owns 8 rows; lane holds 16 LDG.128 in flight.
__global__ void k_scores(const float* __restrict__ enc) {
    __shared__ float w_s[256];
    int t = threadIdx.x;
    int lane = t & 31, wid = t >> 5;

    w_s[t] = g_wpart[t] + g_wpart[256 + t] + g_wpart[512 + t] + g_wpart[768 + t];
    __syncthreads();

    int gw = blockIdx.x * 8 + wid;
    int r0 = gw * 8;                   // global row index (b*LL + l)
    const float4* w4 = (const float4*)w_s;
    float4 wa = w4[lane];
    float4 wb = w4[32 + lane];
    float4 a[8], c[8];
    #pragma unroll
    for (int j = 0; j < 8; j++) {
        const float4* p = (const float4*)(enc + (size_t)(r0 + j) * HH);
        a[j] = p[lane];
        c[j] = p[32 + lane];
    }
    #pragma unroll
    for (int j = 0; j < 8; j++) {
        float s = a[j].x * wa.x + a[j].y * wa.y + a[j].z * wa.z + a[j].w * wa.w
                + c[j].x * wb.x + c[j].y * wb.y + c[j].z * wb.z + c[j].w * wb.w;
        #pragma unroll
        for (int off = 16; off > 0; off >>= 1)
            s += __shfl_xor_sync(0xffffffffu, s, off);
        if (lane == 0) g_scores[r0 + j] = s;
    }
}

// ---------------- K3: exact per-b softmax -> normalized weights in d_out ----------------
__global__ void k_softmax(float* __restrict__ out) {
    __shared__ float red[256];
    int b = blockIdx.x, t = threadIdx.x;
    const float4* sc4 = (const float4*)(g_scores + b * LL);
    float4 s[2];
    s[0] = sc4[t * 2];
    s[1] = sc4[t * 2 + 1];
    float m = fmaxf(fmaxf(s[0].x, s[0].y), fmaxf(s[0].z, s[0].w));
    m = fmaxf(m, fmaxf(fmaxf(s[1].x, s[1].y), fmaxf(s[1].z, s[1].w)));
    red[t] = m; __syncthreads();
    for (int o = 128; o > 0; o >>= 1) { if (t < o) red[t] = fmaxf(red[t], red[t + o]); __syncthreads(); }
    m = red[0]; __syncthreads();
    float4 e[2];
    e[0].x = expf(s[0].x - m); e[0].y = expf(s[0].y - m);
    e[0].z = expf(s[0].z - m); e[0].w = expf(s[0].w - m);
    e[1].x = expf(s[1].x - m); e[1].y = expf(s[1].y - m);
    e[1].z = expf(s[1].z - m); e[1].w = expf(s[1].w - m);
    float sum = (e[0].x + e[0].y) + (e[0].z + e[0].w)
              + (e[1].x + e[1].y) + (e[1].z + e[1].w);
    red[t] = sum; __syncthreads();
    for (int o = 128; o > 0; o >>= 1) { if (t < o) red[t] += red[t + o]; __syncthreads(); }
    float inv = 1.0f / red[0];
    float4* o4 = (float4*)(out + OUT_AW + b * LL);
    e[0].x *= inv; e[0].y *= inv; e[0].z *= inv; e[0].w *= inv;
    e[1].x *= inv; e[1].y *= inv; e[1].z *= inv; e[1].w *= inv;
    o4[t * 2] = e[0];
    o4[t * 2 + 1] = e[1];
}

// ---------------- K4: weighted partial sums (enc L2-resident second pass) ----------------
// grid (32 chunks, 32 b); thread: hq = float4-lane over H, lg = l-group.
__global__ void k_attnpart(const float* __restrict__ enc, const float* __restrict__ out) {
    int c = blockIdx.x, b = blockIdx.y;
    int t = threadIdx.x;
    int hq = t & 63, lg = t >> 6;
    int base = b * LL + c * 64 + lg;
    const float4* e4 = (const float4*)enc;
    float4 a0 = make_float4(0, 0, 0, 0), a1 = a0, a2 = a0, a3 = a0;
    #pragma unroll
    for (int j = 0; j < 64; j += 16) {
        int l0 = base + j;
        float w0 = out[OUT_AW + l0 + 0];
        float w1 = out[OUT_AW + l0 + 4];
        float w2 = out[OUT_AW + l0 + 8];
        float w3 = out[OUT_AW + l0 + 12];
        float4 e0 = e4[(size_t)(l0 + 0)  * 64 + hq];
        float4 e1 = e4[(size_t)(l0 + 4)  * 64 + hq];
        float4 e2 = e4[(size_t)(l0 + 8)  * 64 + hq];
        float4 e3 = e4[(size_t)(l0 + 12) * 64 + hq];
        a0.x = fmaf(w0, e0.x, a0.x); a0.y = fmaf(w0, e0.y, a0.y);
        a0.z = fmaf(w0, e0.z, a0.z); a0.w = fmaf(w0, e0.w, a0.w);
        a1.x = fmaf(w1, e1.x, a1.x); a1.y = fmaf(w1, e1.y, a1.y);
        a1.z = fmaf(w1, e1.z, a1.z); a1.w = fmaf(w1, e1.w, a1.w);
        a2.x = fmaf(w2, e2.x, a2.x); a2.y = fmaf(w2, e2.y, a2.y);
        a2.z = fmaf(w2, e2.z, a2.z); a2.w = fmaf(w2, e2.w, a2.w);
        a3.x = fmaf(w3, e3.x, a3.x); a3.y = fmaf(w3, e3.y, a3.y);
        a3.z = fmaf(w3, e3.z, a3.z); a3.w = fmaf(w3, e3.w, a3.w);
    }
    __shared__ float4 sm[4][64];
    float4 s;
    s.x = (a0.x + a1.x) + (a2.x + a3.x);
    s.y = (a0.y + a1.y) + (a2.y + a3.y);
    s.z = (a0.z + a1.z) + (a2.z + a3.z);
    s.w = (a0.w + a1.w) + (a2.w + a3.w);
    sm[lg][hq] = s;
    __syncthreads();
    if (t < 64) {
        float4 r0 = sm[0][t], r1 = sm[1][t], r2 = sm[2][t], r3 = sm[3][t];
        float4 r;
        r.x = (r0.x + r1.x) + (r2.x + r3.x);
        r.y = (r0.y + r1.y) + (r2.y + r3.y);
        r.z = (r0.z + r1.z) + (r2.z + r3.z);
        r.w = (r0.w + r1.w) + (r2.w + r3.w);
        *(float4*)(g_part + (size_t)(b * NC2 + c) * 256 + 4 * t) = r;
    }
}

// ---------------- K5: reduce attn partials + emb/hidden transpose ----------------
__global__ void kB(const int* __restrict__ tokens,
                   const float* __restrict__ emb_table,
                   const float* __restrict__ hidden) {
    int b = blockIdx.x, t = threadIdx.x;

    int tok = tokens[b];
    g_xT[t * 32 + b] = emb_table[(long long)tok * HH + t];
    g_xT[(512 + t) * 32 + b] = hidden[b * HH + t];

    float s0 = 0, s1 = 0, s2 = 0, s3 = 0;
    #pragma unroll
    for (int c = 0; c < NC2; c += 4) {
        s0 += g_part[(size_t)(b * NC2 + c + 0) * 256 + t];
        s1 += g_part[(size_t)(b * NC2 + c + 1) * 256 + t];
        s2 += g_part[(size_t)(b * NC2 + c + 2) * 256 + t];
        s3 += g_part[(size_t)(b * NC2 + c + 3) * 256 + t];
    }
    float s = (s0 + s1) + (s2 + s3);
    g_x2[b * K2H + 256 + t] = s;
    g_xT[(256 + t) * 32 + b] = s;
}

// ---------------- K6: LSTM gates GEMM — smem-tiled, 256 blocks ----------------
#define GT 32
#define KT 96
__global__ void k_gates(const float* __restrict__ W_ih, const float* __restrict__ b_ih,
                        const float* __restrict__ W_hh, const float* __restrict__ b_hh) {
    __shared__ float Ws[GT * KT];   // 12 KB  [g][k]
    __shared__ float xs[KT * 32];   // 12 KB  [k][b]
    int t = threadIdx.x;
    int g0 = blockIdx.x * GT;
    int ks = blockIdx.y;
    int klo = ks * KT;

    #pragma unroll
    for (int i = 0; i < GT * KT / 256; i++) {
        int idx = t + i * 256;
        int g = idx / KT, kk = idx - g * KT;
        int kg = klo + kk;
        float v = (kg < 512) ? W_ih[(size_t)(g0 + g) * 512 + kg]
                             : W_hh[(size_t)(g0 + g) * 256 + (kg - 512)];
        Ws[g * KT + kk] = v;
    }
    #pragma unroll
    for (int i = 0; i < KT * 32 / 256; i++) {
        int idx = t + i * 256;
        xs[idx] = g_xT[klo * 32 + idx];
    }
    __syncthreads();

    int lane = t & 31, w = t >> 5;
    int gl = w * 4;
    float acc[4] = {0, 0, 0, 0};
    #pragma unroll 4
    for (int kk = 0; kk < KT; kk += 2) {
        float x0 = xs[kk * 32 + lane];
        float x1 = xs[(kk + 1) * 32 + lane];
        #pragma unroll
        for (int g = 0; g < 4; g++) {
            float2 wp = *(const float2*)&Ws[(gl + g) * KT + kk];
            acc[g] = fmaf(wp.x, x0, fmaf(wp.y, x1, acc[g]));
        }
    }
    float* gp = g_gpart + ks * 32768;
    #pragma unroll
    for (int g = 0; g < 4; g++) {
        float a = acc[g];
        int gr = g0 + gl + g;
        if (ks == 0) a += b_ih[gr] + b_hh[gr];
        gp[gr * 32 + lane] = a;
    }
}

// ---------------- K7: LSTM pointwise (sums 8 k-split partials) ----------------
__global__ void k_lstm(const float* __restrict__ cell, float* __restrict__ out) {
    int b = blockIdx.x, h = threadIdx.x;
    float ig = 0, fg = 0, gg = 0, og = 0;
    #pragma unroll
    for (int ks = 0; ks < NKS; ks++) {
        const float* gp = g_gpart + ks * 32768;
        ig += gp[(0 * HH + h) * 32 + b];
        fg += gp[(1 * HH + h) * 32 + b];
        gg += gp[(2 * HH + h) * 32 + b];
        og += gp[(3 * HH + h) * 32 + b];
    }
    float c_new = sigf(fg) * cell[b * HH + h] + sigf(ig) * tanhf(gg);
    float h_new = sigf(og) * tanhf(c_new);
    out[OUT_H + b * HH + h] = h_new;
    out[OUT_C + b * HH + h] = c_new;
    g_x2[b * K2H + h] = h_new;
}

// ---------------- K8: logits GEMM — f32x2 packed over even/odd k, 3 blocks/SM ----------
#define WSD 34
__global__ void __launch_bounds__(256, 3) k_logits(const float* __restrict__ Wo,
                                                   const float* __restrict__ bo,
                                                   float* __restrict__ out) {
    __shared__ float Wt[2][128 * WSD];
    __shared__ float Xs[2][32 * WSD + 8];
    __shared__ float red[32 * 32];        // [vq][b] reduction scratch

    int t = threadIdx.x;
    int v0 = blockIdx.x * 128;
    int vq = t >> 3, bq = t & 7;

    float4 wreg[4];
    float4 xreg;

    auto load_tile = [&](int kt) {
        #pragma unroll
        for (int jj = 0; jj < 4; jj++) {
            int idx = jj * 256 + t;
            int row = idx >> 3, q = idx & 7;
            int vr = v0 + row;
            wreg[jj] = (vr < VV) ? *(const float4*)(Wo + (size_t)vr * 512 + kt + 4 * q)
                                 : make_float4(0.f, 0.f, 0.f, 0.f);
        }
        xreg = *(const float4*)(g_x2 + (t >> 3) * K2H + kt + 4 * (t & 7));
    };
    auto store_tile = [&](int s) {
        #pragma unroll
        for (int jj = 0; jj < 4; jj++) {
            int idx = jj * 256 + t;
            int row = idx >> 3, q = idx & 7;
            float* p = &Wt[s][row * WSD + 4 * q];
            *(float2*)(p)     = make_float2(wreg[jj].x, wreg[jj].y);
            *(float2*)(p + 2) = make_float2(wreg[jj].z, wreg[jj].w);
        }
        int b = t >> 3, q = t & 7;
        float* p = &Xs[s][b * WSD + 4 * q + 2 * ((b >> 4) & 1)];
        *(float2*)(p)     = make_float2(xreg.x, xreg.y);
        *(float2*)(p + 2) = make_float2(xreg.z, xreg.w);
    };

    unsigned long long acc[4][4];
    #pragma unroll
    for (int i = 0; i < 4; i++)
        #pragma unroll
        for (int j = 0; j < 4; j++) acc[i][j] = 0ull;

    load_tile(0);
    store_tile(0);
    __syncthreads();

    for (int it = 0; it < 16; it++) {
        int cur = it & 1;
        if (it < 15) load_tile((it + 1) * 32);
        const float* W = Wt[cur];
        const float* X = Xs[cur];
        #pragma unroll
        for (int kk = 0; kk < 32; kk += 2) {
            unsigned long long wv[4], xv[4];
            #pragma unroll
            for (int i = 0; i < 4; i++)
                wv[i] = *(const unsigned long long*)(W + (vq * 4 + i) * WSD + kk);
            #pragma unroll
            for (int j = 0; j < 4; j++) {
                int bj = bq * 4 + j;
                xv[j] = *(const unsigned long long*)(X + bj * WSD + kk + 2 * ((bj >> 4) & 1));
            }
            #pragma unroll
            for (int i = 0; i < 4; i++)
                #pragma unroll
                for (int j = 0; j < 4; j++)
                    acc[i][j] = ffma2(wv[i], xv[j], acc[i][j]);
        }
        if (it < 15) store_tile(cur ^ 1);
        __syncthreads();
    }

    float lg[4][4];
    float lmax[4] = { -1e30f, -1e30f, -1e30f, -1e30f };
    #pragma unroll
    for (int i = 0; i < 4; i++) {
        int vv = v0 + vq * 4 + i;
        if (vv < VV) {
            float bias = bo[vv];
            #pragma unroll
            for (int j = 0; j < 4; j++) {
                float lo = __uint_as_float((unsigned)(acc[i][j] & 0xffffffffull));
                float hi = __uint_as_float((unsigned)(acc[i][j] >> 32));
                float l = (lo + hi) + bias;
                lg[i][j] = l;
                lmax[j] = fmaxf(lmax[j], l);
                out[(size_t)(bq * 4 + j) * VV + vv] = l;
            }
        } else {
            #pragma unroll
            for (int j = 0; j < 4; j++) lg[i][j] = -1e30f;
        }
    }

    #pragma unroll
    for (int j = 0; j < 4; j++) red[vq * 32 + bq * 4 + j] = lmax[j];
    __syncthreads();
    for (int off = 16; off > 0; off >>= 1) {
        if (vq < off) {
            #pragma unroll
            for (int j = 0; j < 4; j++) {
                int b = bq * 4 + j;
                red[vq * 32 + b] = fmaxf(red[vq * 32 + b], red[(vq + off) * 32 + b]);
            }
        }
        __syncthreads();
    }
    float mb[4];
    #pragma unroll
    for (int j = 0; j < 4; j++) mb[j] = red[bq * 4 + j];
    __syncthreads();

    float lsum[4] = { 0.f, 0.f, 0.f, 0.f };
    #pragma unroll
    for (int i = 0; i < 4; i++)
        #pragma unroll
        for (int j = 0; j < 4; j++)
            if (lg[i][j] > -1e29f) lsum[j] += expf(lg[i][j] - mb[j]);
    #pragma unroll
    for (int j = 0; j < 4; j++) red[vq * 32 + bq * 4 + j] = lsum[j];
    __syncthreads();
    for (int off = 16; off > 0; off >>= 1) {
        if (vq < off) {
            #pragma unroll
            for (int j = 0; j < 4; j++) {
                int b = bq * 4 + j;
                red[vq * 32 + b] += red[(vq + off) * 32 + b];
            }
        }
        __syncthreads();
    }
    if (vq == 0) {
        #pragma unroll
        for (int j = 0; j < 4; j++) {
            int b = bq * 4 + j;
            g_lsem[blockIdx.x * 32 + b] = mb[j];
            g_lses[blockIdx.x * 32 + b] = red[b];
        }
    }
}

// ---------------- K9: merge per-block LSE partials ----------------
__global__ void k_lse() {
    __shared__ float mred[512], sred[512];
    int b = blockIdx.x, t = threadIdx.x;
    float m = -1e30f, S = 0.f;
    if (t < NBLK) {
        m = g_lsem[t * 32 + b];
        S = g_lses[t * 32 + b];
    }
    mred[t] = m; sred[t] = S;
    __syncthreads();
    for (int off = 256; off > 0; off >>= 1) {
        if (t < off) {
            float m1 = mred[t], m2 = mred[t + off];
            float s1 = sred[t], s2 = sred[t + off];
            float mm = fmaxf(m1, m2);
            mred[t] = mm;
            sred[t] = s1 * expf(m1 - mm) + s2 * expf(m2 - mm);
        }
        __syncthreads();
    }
    if (t == 0) g_lse[b] = mred[0] + logf(sred[0]);
}

// ---------------- K10: log_probs -= lse, flat float4 (B*V divisible by 4) ----------------
__global__ void k_sub(float* __restrict__ out) {
    const int NF4 = (BB * VV) / 4;        // 402056
    int base = blockIdx.x * 1024 + threadIdx.x;
    float4* o4 = (float4*)out;
    #pragma unroll
    for (int j = 0; j < 4; j++) {
        int f = base + j * 256;
        if (f < NF4) {
            int e0 = f * 4;
            int b0 = e0 / VV;
            int bnd = (b0 + 1) * VV;
            float l0 = g_lse[b0];
            float l1 = (b0 < BB - 1) ? g_lse[b0 + 1] : 0.f;
            float4 v = o4[f];
            v.x -= (e0 + 0 >= bnd) ? l1 : l0;
            v.y -= (e0 + 1 >= bnd) ? l1 : l0;
            v.z -= (e0 + 2 >= bnd) ? l1 : l0;
            v.w -= (e0 + 3 >= bnd) ? l1 : l0;
            o4[f] = v;
        }
    }
}

extern "C" void kernel_launch(void* const* d_in, const int* in_sizes, int n_in,
                              void* d_out, int out_size) {
    const int*   tokens    = (const int*)d_in[0];
    const float* hidden    = (const float*)d_in[1];
    const float* cell      = (const float*)d_in[2];
    const float* enc       = (const float*)d_in[3];
    const float* emb_table = (const float*)d_in[4];
    const float* W_attn    = (const float*)d_in[5];
    // d_in[6] = b_attn unused (softmax shift-invariance)
    const float* vvec      = (const float*)d_in[7];
    const float* W_ih      = (const float*)d_in[8];
    const float* b_ih      = (const float*)d_in[9];
    const float* W_hh      = (const float*)d_in[10];
    const float* b_hh      = (const float*)d_in[11];
    const float* W_out     = (const float*)d_in[12];
    const float* b_out     = (const float*)d_in[13];
    float* out = (float*)d_out;

    k_init<<<4, 256>>>(W_attn, vvec);                                    // 1
    k_scores<<<1024, 256>>>(enc);                                        // 2
    k_softmax<<<BB, 256>>>(out);                                         // 3
    {
        dim3 g(NC2, BB);
        k_attnpart<<<g, 256>>>(enc, out);                                // 4
    }
    kB<<<BB, 256>>>(tokens, emb_table, hidden);                          // 5
    {
        dim3 g(1024 / GT, NKS);
        k_gates<<<g, 256>>>(W_ih, b_ih, W_hh, b_hh);                     // 6
    }
    k_lstm<<<BB, 256>>>(cell, out);                                      // 7
    k_logits<<<NBLK, 256>>>(W_out, b_out, out);                          // 8
    k_lse<<<BB, 512>>>();                                                // 9
    {
        const int NF4 = (BB * VV) / 4;
        k_sub<<<(NF4 + 1023) / 1024, 256>>>(out);                        // 10
    }
}